// round 3
// baseline (speedup 1.0000x reference)
#include <cuda_runtime.h>
#include <math.h>

// RepulsionLoss: points [4, 8192, 3] f32 -> scalar f32
// Fused brute-force KNN (K=8) + loss reduction.
//
// R3: hot loop = packed f32x2 distances + threshold test only.
//  - smem tiles hold NEGATED candidate coords as pairs (ull = 2 floats)
//  - passing d2 values captured into per-thread smem buffer behind a
//    warp-uniform __any_sync branch (no 14-op predicated insert per cand)
//  - sorted top-8 maintained only at buffer flushes
//  - single kernel: last-block ticket does final scale + restores globals

#define BATCH   4
#define NPTS    8192
#define KNN     8
#define RADIUS  0.07f
#define H2_INV  (1.0f / (0.03f * 0.03f))
#define ALPHA   0.1f

#define NSLICE   8                  // warps per block = candidate slices
#define SLICE_N  (NPTS / NSLICE)    // 1024 candidates per slice
#define TILE_P   128                // pairs per tile (= 256 candidates)
#define TILE_C   (2 * TILE_P)
#define BLOCK    (32 * NSLICE)      // 256 threads
#define QPB      32                 // queries per block (one per lane)
#define CAP      12                 // per-thread capture buffer entries
#define GRID     (BATCH * (NPTS / QPB))   // 1024 blocks

__device__ float        g_acc;      // zero-initialized; restored by last block
__device__ unsigned int g_tick;     // ditto

typedef unsigned long long ull;

static __device__ __forceinline__ ull pack2(float lo, float hi) {
    ull r; asm("mov.b64 %0, {%1,%2};" : "=l"(r) : "f"(lo), "f"(hi)); return r;
}
static __device__ __forceinline__ void unpack2(ull v, float& lo, float& hi) {
    asm("mov.b64 {%0,%1}, %2;" : "=f"(lo), "=f"(hi) : "l"(v));
}
static __device__ __forceinline__ ull add2(ull a, ull b) {
    ull r; asm("add.rn.f32x2 %0, %1, %2;" : "=l"(r) : "l"(a), "l"(b)); return r;
}
static __device__ __forceinline__ ull mul2(ull a, ull b) {
    ull r; asm("mul.rn.f32x2 %0, %1, %2;" : "=l"(r) : "l"(a), "l"(b)); return r;
}
static __device__ __forceinline__ ull fma2(ull a, ull b, ull c) {
    ull r; asm("fma.rn.f32x2 %0, %1, %2, %3;" : "=l"(r) : "l"(a), "l"(b), "l"(c)); return r;
}

__global__ __launch_bounds__(BLOCK) void repulsion_knn_kernel(
        const float* __restrict__ pts, float* __restrict__ out) {
    __shared__ ull   s_x[NSLICE][TILE_P];            // 8 KB  (negated x pairs)
    __shared__ ull   s_y[NSLICE][TILE_P];            // 8 KB
    __shared__ ull   s_z[NSLICE][TILE_P];            // 8 KB
    __shared__ float s_buf[CAP][BLOCK];              // 12 KB capture buffers
    __shared__ float s_merge[QPB][NSLICE * KNN + 1]; // 8.3 KB (stride 65)

    const int w = threadIdx.x >> 5;    // slice / warp id
    const int l = threadIdx.x & 31;    // lane = local query id
    const int tid = threadIdx.x;

    const int blocks_per_batch = NPTS / QPB;           // 256
    const int b  = blockIdx.x / blocks_per_batch;
    const int qg = blockIdx.x % blocks_per_batch;
    const int q  = qg * QPB + l;

    const float* __restrict__ base = pts + (size_t)b * NPTS * 3;

    const float qx = base[q * 3 + 0];
    const float qy = base[q * 3 + 1];
    const float qz = base[q * 3 + 2];
    const ull qx2 = pack2(qx, qx);
    const ull qy2 = pack2(qy, qy);
    const ull qz2 = pack2(qz, qz);

    float best[KNN];                  // sorted ascending
#pragma unroll
    for (int k = 0; k < KNN; ++k) best[k] = 3.0e38f;
    float thr = 3.0e38f;
    int cnt = 0;

    const int c0 = w * SLICE_N;

    for (int t0 = 0; t0 < SLICE_N; t0 += TILE_C) {
        // per-warp tile fill: pair p <- candidates (c0+t0+2p, +1), negated
#pragma unroll
        for (int r = 0; r < TILE_P / 32; ++r) {
            const int p  = r * 32 + l;
            const int j0 = c0 + t0 + 2 * p;
            const float2* gp = (const float2*)(base + 3 * (size_t)j0);
            const float2 a = gp[0];   // {x0, y0}
            const float2 bb = gp[1];  // {z0, x1}
            const float2 c = gp[2];   // {y1, z1}
            s_x[w][p] = pack2(-a.x, -bb.y);
            s_y[w][p] = pack2(-a.y, -c.x);
            s_z[w][p] = pack2(-bb.x, -c.y);
        }
        __syncwarp();

#pragma unroll 4
        for (int p = 0; p < TILE_P; ++p) {
            const ull dx2 = add2(qx2, s_x[w][p]);     // {qx-x0, qx-x1}
            const ull dy2 = add2(qy2, s_y[w][p]);
            const ull dz2 = add2(qz2, s_z[w][p]);
            ull d2p = mul2(dx2, dx2);
            d2p = fma2(dy2, dy2, d2p);
            d2p = fma2(dz2, dz2, d2p);
            float d2lo, d2hi;
            unpack2(d2p, d2lo, d2hi);
            const float pm = fminf(d2lo, d2hi);
            if (__any_sync(0xffffffffu, pm < thr)) {
                // rare, warp-uniform branch: capture passing halves
                if (d2lo < thr) {
                    s_buf[cnt][tid] = d2lo;
                    if (++cnt == CAP) {   // overflow flush
#pragma unroll 4
                        for (int i = 0; i < CAP; ++i) {
                            const float v = s_buf[i][tid];
                            if (v < best[KNN - 1]) {
                                best[KNN - 1] = v;
#pragma unroll
                                for (int k = KNN - 1; k > 0; --k) {
                                    const float lo = fminf(best[k - 1], best[k]);
                                    const float hi = fmaxf(best[k - 1], best[k]);
                                    best[k - 1] = lo; best[k] = hi;
                                }
                            }
                        }
                        cnt = 0; thr = best[KNN - 1];
                    }
                }
                if (d2hi < thr) {
                    s_buf[cnt][tid] = d2hi;
                    if (++cnt == CAP) {
#pragma unroll 4
                        for (int i = 0; i < CAP; ++i) {
                            const float v = s_buf[i][tid];
                            if (v < best[KNN - 1]) {
                                best[KNN - 1] = v;
#pragma unroll
                                for (int k = KNN - 1; k > 0; --k) {
                                    const float lo = fminf(best[k - 1], best[k]);
                                    const float hi = fmaxf(best[k - 1], best[k]);
                                    best[k - 1] = lo; best[k] = hi;
                                }
                            }
                        }
                        cnt = 0; thr = best[KNN - 1];
                    }
                }
            }
        }

        // end-of-tile flush tightens thr for next tile
        if (__any_sync(0xffffffffu, cnt > 0)) {
            for (int i = 0; i < cnt; ++i) {
                const float v = s_buf[i][tid];
                if (v < best[KNN - 1]) {
                    best[KNN - 1] = v;
#pragma unroll
                    for (int k = KNN - 1; k > 0; --k) {
                        const float lo = fminf(best[k - 1], best[k]);
                        const float hi = fmaxf(best[k - 1], best[k]);
                        best[k - 1] = lo; best[k] = hi;
                    }
                }
            }
            cnt = 0; thr = best[KNN - 1];
        }
        __syncwarp();
    }

    // publish this slice's top-8
#pragma unroll
    for (int k = 0; k < KNN; ++k) s_merge[l][w * KNN + k] = best[k];
    __syncthreads();

    // warp 0: exact global top-8 per query from the 8 slice top-8s
    if (w == 0) {
        float m[KNN];
#pragma unroll
        for (int k = 0; k < KNN; ++k) m[k] = 3.0e38f;
        for (int i = 0; i < NSLICE * KNN; ++i) {
            const float d2 = s_merge[l][i];
            if (d2 < m[KNN - 1]) {
                m[KNN - 1] = d2;
#pragma unroll
                for (int k = KNN - 1; k > 0; --k) {
                    const float lo = fminf(m[k - 1], m[k]);
                    const float hi = fmaxf(m[k - 1], m[k]);
                    m[k - 1] = lo; m[k] = hi;
                }
            }
        }

        float s = 0.0f;
#pragma unroll
        for (int k = 0; k < KNN; ++k) {
            const float d2 = m[k];
            const float dn = sqrtf(fmaxf(d2, 1e-12f));
            const float wgt = __expf(-d2 * H2_INV);
            s = fmaf(RADIUS - dn, wgt, s);
        }
#pragma unroll
        for (int off = 16; off > 0; off >>= 1)
            s += __shfl_xor_sync(0xffffffffu, s, off);

        if (l == 0) {
            atomicAdd(&g_acc, s);
            __threadfence();
            const unsigned t = atomicAdd(&g_tick, 1u);
            if (t == GRID - 1) {           // last block finalizes
                __threadfence();
                const float total = atomicAdd(&g_acc, 0.0f);   // ordered read
                out[0] = ALPHA * total * (1.0f / (float)(BATCH * NPTS * KNN));
                // restore globals for the next graph replay
                g_acc  = 0.0f;
                __threadfence();
                g_tick = 0u;
            }
        }
    }
}

extern "C" void kernel_launch(void* const* d_in, const int* in_sizes, int n_in,
                              void* d_out, int out_size) {
    const float* pts = (const float*)d_in[0];
    float* out = (float*)d_out;
    repulsion_knn_kernel<<<GRID, BLOCK>>>(pts, out);
}

// round 4
// speedup vs baseline: 8.2305x; 8.2305x over previous
#include <cuda_runtime.h>
#include <math.h>

// RepulsionLoss: points [4, 8192, 3] f32 -> scalar f32
// R4: spatial-grid KNN. Cell = 1/12 (0.0833). Each query scans its 3x3x3
// cell block (~128 candidates) instead of all 8192. Any true neighbor
// missed by the block has dn > 0.0833 -> weight < 4.4e-4 -> contribution
// < 6e-6 per term vs mean term ~1.5e-2: rel error << 1e-3 tolerance.
//
// Pipeline (one CUDA-graph, 5 kernels, all scratch in __device__ globals):
//   1. zero counts   2. count points per cell   3. per-batch block scan
//   4. scatter into cell-sorted float4 array    5. fused KNN + loss
// Kernel 5 finalizes via ticket and restores globals for graph replay.

#define BATCH   4
#define NPTS    8192
#define KNN     8
#define RADIUS  0.07f
#define H2_INV  (1.0f / (0.03f * 0.03f))
#define ALPHA   0.1f

#define GRIDC   12
#define NCELL   (GRIDC * GRIDC * GRIDC)   // 1728
#define CPAD    2048                      // padded for scan

#define KBLOCK  128
#define KGRID   (BATCH * NPTS / KBLOCK)   // 256 blocks

__device__ int    g_cnt[BATCH][CPAD];
__device__ int    g_off[BATCH][CPAD];
__device__ int    g_cur[BATCH][CPAD];
__device__ float4 g_sorted[BATCH][NPTS];
__device__ float        g_acc;    // zero-init; restored by finalize
__device__ unsigned int g_tick;   // ditto

static __device__ __forceinline__ int cell_coord(float v) {
    int c = (int)(v * (float)GRIDC);
    return c > GRIDC - 1 ? GRIDC - 1 : (c < 0 ? 0 : c);
}

// ---- 1: zero counts (4 x 2048 ints) ------------------------------------
__global__ void zero_kernel() {
    const int i = blockIdx.x * blockDim.x + threadIdx.x;   // 0..8191
    ((int*)g_cnt)[i] = 0;
}

// ---- 2: histogram ------------------------------------------------------
__global__ void count_kernel(const float* __restrict__ pts) {
    const int i = blockIdx.x * blockDim.x + threadIdx.x;   // 0..BATCH*NPTS-1
    const int b = i / NPTS;
    const float x = pts[(size_t)i * 3 + 0];
    const float y = pts[(size_t)i * 3 + 1];
    const float z = pts[(size_t)i * 3 + 2];
    const int c = (cell_coord(z) * GRIDC + cell_coord(y)) * GRIDC + cell_coord(x);
    atomicAdd(&g_cnt[b][c], 1);
}

// ---- 3: per-batch exclusive scan (block = 1024 thr, 2 cells/thread) ----
__global__ __launch_bounds__(1024) void scan_kernel() {
    __shared__ int s[1024];
    const int b = blockIdx.x;
    const int t = threadIdx.x;
    const int a0 = g_cnt[b][2 * t];
    const int a1 = g_cnt[b][2 * t + 1];
    const int sum = a0 + a1;
    s[t] = sum;
    __syncthreads();
    for (int off = 1; off < 1024; off <<= 1) {
        const int v = (t >= off) ? s[t - off] : 0;
        __syncthreads();
        s[t] += v;
        __syncthreads();
    }
    const int ex = s[t] - sum;        // exclusive prefix of this thread's pair
    g_off[b][2 * t]     = ex;
    g_off[b][2 * t + 1] = ex + a0;
    g_cur[b][2 * t]     = ex;
    g_cur[b][2 * t + 1] = ex + a0;
}

// ---- 4: scatter into cell-sorted array ---------------------------------
__global__ void scatter_kernel(const float* __restrict__ pts) {
    const int i = blockIdx.x * blockDim.x + threadIdx.x;
    const int b = i / NPTS;
    const float x = pts[(size_t)i * 3 + 0];
    const float y = pts[(size_t)i * 3 + 1];
    const float z = pts[(size_t)i * 3 + 2];
    const int c = (cell_coord(z) * GRIDC + cell_coord(y)) * GRIDC + cell_coord(x);
    const int pos = atomicAdd(&g_cur[b][c], 1);
    g_sorted[b][pos] = make_float4(x, y, z, 0.0f);
}

// ---- 5: fused grid-KNN + loss ------------------------------------------
__global__ __launch_bounds__(KBLOCK) void knn_kernel(float* __restrict__ out) {
    __shared__ float s_warp[KBLOCK / 32];

    const int blocks_per_batch = NPTS / KBLOCK;
    const int b  = blockIdx.x / blocks_per_batch;
    const int qi = (blockIdx.x % blocks_per_batch) * KBLOCK + threadIdx.x;

    const float4 p = g_sorted[b][qi];
    const float qx = p.x, qy = p.y, qz = p.z;
    const int cx = cell_coord(qx);
    const int cy = cell_coord(qy);
    const int cz = cell_coord(qz);

    float best[KNN];                 // sorted ascending
#pragma unroll
    for (int k = 0; k < KNN; ++k) best[k] = 3.0e38f;

    const int x0 = (cx > 0 ? cx - 1 : 0);
    const int x1 = (cx < GRIDC - 1 ? cx + 1 : GRIDC - 1);
    const int y0 = (cy > 0 ? cy - 1 : 0);
    const int y1 = (cy < GRIDC - 1 ? cy + 1 : GRIDC - 1);
    const int z0 = (cz > 0 ? cz - 1 : 0);
    const int z1 = (cz < GRIDC - 1 ? cz + 1 : GRIDC - 1);

    for (int zz = z0; zz <= z1; ++zz) {
        for (int yy = y0; yy <= y1; ++yy) {
            const int rowbase = (zz * GRIDC + yy) * GRIDC;
            const int js = g_off[b][rowbase + x0];
            const int je = g_off[b][rowbase + x1 + 1];
#pragma unroll 2
            for (int j = js; j < je; ++j) {
                const float4 c = g_sorted[b][j];
                const float dx = qx - c.x;
                const float dy = qy - c.y;
                const float dz = qz - c.z;
                const float d2 = fmaf(dx, dx, fmaf(dy, dy, dz * dz));
                if (d2 < best[KNN - 1]) {
                    best[KNN - 1] = d2;
#pragma unroll
                    for (int k = KNN - 1; k > 0; --k) {
                        const float lo = fminf(best[k - 1], best[k]);
                        const float hi = fmaxf(best[k - 1], best[k]);
                        best[k - 1] = lo;
                        best[k]     = hi;
                    }
                }
            }
        }
    }

    // loss terms; unfilled slots (best = 3e38) give exp(-inf)=0 -> contribute 0
    float s = 0.0f;
#pragma unroll
    for (int k = 0; k < KNN; ++k) {
        const float d2 = best[k];
        const float dn = sqrtf(fmaxf(d2, 1e-12f));
        const float w  = __expf(-d2 * H2_INV);
        s = fmaf(RADIUS - dn, w, s);
    }

#pragma unroll
    for (int off = 16; off > 0; off >>= 1)
        s += __shfl_xor_sync(0xffffffffu, s, off);
    if ((threadIdx.x & 31) == 0) s_warp[threadIdx.x >> 5] = s;
    __syncthreads();

    if (threadIdx.x == 0) {
        float bs = 0.0f;
#pragma unroll
        for (int w = 0; w < KBLOCK / 32; ++w) bs += s_warp[w];
        atomicAdd(&g_acc, bs);
        __threadfence();
        const unsigned t = atomicAdd(&g_tick, 1u);
        if (t == KGRID - 1) {                     // last block finalizes
            __threadfence();
            const float total = atomicAdd(&g_acc, 0.0f);
            out[0] = ALPHA * total * (1.0f / (float)(BATCH * NPTS * KNN));
            g_acc = 0.0f;                          // restore for graph replay
            __threadfence();
            g_tick = 0u;
        }
    }
}

extern "C" void kernel_launch(void* const* d_in, const int* in_sizes, int n_in,
                              void* d_out, int out_size) {
    const float* pts = (const float*)d_in[0];
    float* out = (float*)d_out;

    zero_kernel   <<<BATCH * CPAD / 1024, 1024>>>();
    count_kernel  <<<BATCH * NPTS / 256, 256>>>(pts);
    scan_kernel   <<<BATCH, 1024>>>();
    scatter_kernel<<<BATCH * NPTS / 256, 256>>>(pts);
    knn_kernel    <<<KGRID, KBLOCK>>>(out);
}

// round 5
// speedup vs baseline: 9.4863x; 1.1526x over previous
#include <cuda_runtime.h>
#include <math.h>

// RepulsionLoss: points [4, 8192, 3] f32 -> scalar f32
// R5: (a) fused single-kernel grid build (count+scan+scatter in smem),
//     (b) KNN split 3 ways per query (one z-plane per thread) for occupancy,
//         exact top-8 recovered by smem merge. 2 kernel launches total.

#define BATCH   4
#define NPTS    8192
#define KNN     8
#define RADIUS  0.07f
#define H2_INV  (1.0f / (0.03f * 0.03f))
#define ALPHA   0.1f

#define GRIDC   12
#define CPAD    2048                      // >= NCELL+1, power of two for scan

#define QPB     128                       // queries per knn block
#define NPLANE  3
#define KBLOCK  (QPB * NPLANE)            // 384 threads
#define KGRID   (BATCH * NPTS / QPB)      // 256 blocks

#define PPT     8                         // points per thread in build (8192/1024)

__device__ int    g_off[BATCH][CPAD];
__device__ float4 g_sorted[BATCH][NPTS];
__device__ float        g_acc;            // zero-init; restored by finalize
__device__ unsigned int g_tick;           // ditto

static __device__ __forceinline__ int cell_coord(float v) {
    int c = (int)(v * (float)GRIDC);
    return c > GRIDC - 1 ? GRIDC - 1 : (c < 0 ? 0 : c);
}

// ---- 1: fused build: histogram + scan + scatter (1 block per batch) ----
__global__ __launch_bounds__(1024) void build_kernel(const float* __restrict__ pts) {
    __shared__ int s_cnt[CPAD];       // counts -> then scatter cursors
    __shared__ int s_wsum[32];

    const int b   = blockIdx.x;
    const int tid = threadIdx.x;
    const int lane = tid & 31;
    const int warp = tid >> 5;
    const float* __restrict__ base = pts + (size_t)b * NPTS * 3;

    for (int i = tid; i < CPAD; i += 1024) s_cnt[i] = 0;
    __syncthreads();

    float px[PPT], py[PPT], pz[PPT];
    int   pc[PPT];
#pragma unroll
    for (int r = 0; r < PPT; ++r) {
        const int i = r * 1024 + tid;
        px[r] = __ldg(base + 3 * i + 0);
        py[r] = __ldg(base + 3 * i + 1);
        pz[r] = __ldg(base + 3 * i + 2);
        pc[r] = (cell_coord(pz[r]) * GRIDC + cell_coord(py[r])) * GRIDC
                + cell_coord(px[r]);
        atomicAdd(&s_cnt[pc[r]], 1);
    }
    __syncthreads();

    // exclusive scan of 2048 counts (2 per thread) via warp shfl
    const int v0 = s_cnt[2 * tid];
    const int v1 = s_cnt[2 * tid + 1];
    int sum = v0 + v1;
    int inc = sum;
#pragma unroll
    for (int off = 1; off < 32; off <<= 1) {
        const int n = __shfl_up_sync(0xffffffffu, inc, off);
        if (lane >= off) inc += n;
    }
    if (lane == 31) s_wsum[warp] = inc;
    __syncthreads();
    if (warp == 0) {
        int wv = s_wsum[lane];
#pragma unroll
        for (int off = 1; off < 32; off <<= 1) {
            const int n = __shfl_up_sync(0xffffffffu, wv, off);
            if (lane >= off) wv += n;
        }
        s_wsum[lane] = wv;
    }
    __syncthreads();
    const int base_w = (warp > 0) ? s_wsum[warp - 1] : 0;
    const int ex = base_w + inc - sum;   // exclusive prefix of this pair
    __syncthreads();                      // counts fully read before overwrite
    s_cnt[2 * tid]     = ex;              // becomes scatter cursor
    s_cnt[2 * tid + 1] = ex + v0;
    g_off[b][2 * tid]     = ex;
    g_off[b][2 * tid + 1] = ex + v0;
    __syncthreads();

#pragma unroll
    for (int r = 0; r < PPT; ++r) {
        const int pos = atomicAdd(&s_cnt[pc[r]], 1);
        g_sorted[b][pos] = make_float4(px[r], py[r], pz[r], 0.0f);
    }
}

// ---- 2: fused grid-KNN + loss (3 z-planes per query, one per thread) ----
__global__ __launch_bounds__(KBLOCK) void knn_kernel(float* __restrict__ out) {
    __shared__ float s_m[QPB][NPLANE * KNN + 1];   // stride 25: conflict-free
    __shared__ float s_warp[4];

    const int tid    = threadIdx.x;
    const int pi     = tid / QPB;       // plane index 0..2
    const int qlocal = tid % QPB;

    const int blocks_per_batch = NPTS / QPB;        // 64
    const int b  = blockIdx.x / blocks_per_batch;
    const int qi = (blockIdx.x % blocks_per_batch) * QPB + qlocal;

    const float4 p = __ldg(&g_sorted[b][qi]);
    const float qx = p.x, qy = p.y, qz = p.z;
    const int cx = cell_coord(qx);
    const int cy = cell_coord(qy);
    const int cz = cell_coord(qz);

    const int x0 = (cx > 0 ? cx - 1 : 0);
    const int x1 = (cx < GRIDC - 1 ? cx + 1 : GRIDC - 1);
    const int y0 = (cy > 0 ? cy - 1 : 0);
    const int y1 = (cy < GRIDC - 1 ? cy + 1 : GRIDC - 1);
    const int z0 = (cz > 0 ? cz - 1 : 0);
    const int z1 = (cz < GRIDC - 1 ? cz + 1 : GRIDC - 1);

    float best[KNN];                    // sorted ascending
#pragma unroll
    for (int k = 0; k < KNN; ++k) best[k] = 3.0e38f;

    const int zz = z0 + pi;
    if (zz <= z1) {
        for (int yy = y0; yy <= y1; ++yy) {
            const int rowbase = (zz * GRIDC + yy) * GRIDC;
            const int js = g_off[b][rowbase + x0];
            const int je = g_off[b][rowbase + x1 + 1];
#pragma unroll 2
            for (int j = js; j < je; ++j) {
                const float4 c = __ldg(&g_sorted[b][j]);
                const float dx = qx - c.x;
                const float dy = qy - c.y;
                const float dz = qz - c.z;
                const float d2 = fmaf(dx, dx, fmaf(dy, dy, dz * dz));
                if (d2 < best[KNN - 1]) {
                    best[KNN - 1] = d2;
#pragma unroll
                    for (int k = KNN - 1; k > 0; --k) {
                        const float lo = fminf(best[k - 1], best[k]);
                        const float hi = fmaxf(best[k - 1], best[k]);
                        best[k - 1] = lo;
                        best[k]     = hi;
                    }
                }
            }
        }
    }

    // publish partial top-8 per plane
#pragma unroll
    for (int k = 0; k < KNN; ++k) s_m[qlocal][pi * KNN + k] = best[k];
    __syncthreads();

    float s = 0.0f;
    if (pi == 0) {
        // exact top-8 over the 3 plane-partials (planes partition candidates)
        float m[KNN];
#pragma unroll
        for (int k = 0; k < KNN; ++k) m[k] = best[k];   // own plane already in regs
        for (int i = KNN; i < NPLANE * KNN; ++i) {
            const float d2 = s_m[qlocal][i];
            if (d2 < m[KNN - 1]) {
                m[KNN - 1] = d2;
#pragma unroll
                for (int k = KNN - 1; k > 0; --k) {
                    const float lo = fminf(m[k - 1], m[k]);
                    const float hi = fmaxf(m[k - 1], m[k]);
                    m[k - 1] = lo;
                    m[k]     = hi;
                }
            }
        }
        // unfilled slots (3e38) -> exp underflows to 0 -> contribute nothing
#pragma unroll
        for (int k = 0; k < KNN; ++k) {
            const float d2 = m[k];
            const float dn = sqrtf(fmaxf(d2, 1e-12f));
            const float w  = __expf(-d2 * H2_INV);
            s = fmaf(RADIUS - dn, w, s);
        }
#pragma unroll
        for (int off = 16; off > 0; off >>= 1)
            s += __shfl_xor_sync(0xffffffffu, s, off);
        if ((tid & 31) == 0) s_warp[tid >> 5] = s;   // warps 0..3 only
    }
    __syncthreads();

    if (tid == 0) {
        const float bs = s_warp[0] + s_warp[1] + s_warp[2] + s_warp[3];
        atomicAdd(&g_acc, bs);
        __threadfence();
        const unsigned t = atomicAdd(&g_tick, 1u);
        if (t == KGRID - 1) {                 // last block finalizes
            __threadfence();
            const float total = atomicAdd(&g_acc, 0.0f);
            out[0] = ALPHA * total * (1.0f / (float)(BATCH * NPTS * KNN));
            g_acc = 0.0f;                      // restore for graph replay
            __threadfence();
            g_tick = 0u;
        }
    }
}

extern "C" void kernel_launch(void* const* d_in, const int* in_sizes, int n_in,
                              void* d_out, int out_size) {
    const float* pts = (const float*)d_in[0];
    float* out = (float*)d_out;

    build_kernel<<<BATCH, 1024>>>(pts);
    knn_kernel  <<<KGRID, KBLOCK>>>(out);
}